// round 11
// baseline (speedup 1.0000x reference)
#include <cuda_runtime.h>
#include <cstdint>

// Row-wise top-k(=6) thresholded renormalization.
//   delta = (6th largest of row) + 1e-7
//   w     = max(v - delta, 0) ;  out = w / (sum(w) + 1e-7)
//
// R11: TWO rows per warp, all 16 LDG.128 front-batched (MLP=16) so row 1's
// loads overlap row 0's selection/epilogue (the memory-silent window that
// capped DRAM at 76%). Selection per row unchanged from R10:
//   t    = 6th largest DISTINCT thread-max (ballot-free; provably <= v6)
//   cand = all elements >= t (full-row shared buffer => exact for ANY input)
//   v6   = 6th largest of cand (lane-0 insertion top-6, exact multiset)

#define COLS   1024
#define TOPK   6
#define EPSV   1e-7f
#define WPB    4            // warps per block; each warp owns 2 rows
#define RPB    (WPB * 2)    // rows per block

__device__ __forceinline__ unsigned redux_max_u32(unsigned v) {
    unsigned r;
    asm volatile("redux.sync.max.u32 %0, %1, %2;"
                 : "=r"(r) : "r"(v), "r"(0xffffffffu));
    return r;
}
// monotone bijection: float ordering -> u32 ordering (exact, invertible)
__device__ __forceinline__ unsigned fkey(float f) {
    unsigned b = __float_as_uint(f);
    return b ^ ((unsigned)((int)b >> 31) | 0x80000000u);
}
__device__ __forceinline__ float funkey(unsigned k) {
    unsigned b = (k & 0x80000000u) ? (k ^ 0x80000000u) : ~k;
    return __uint_as_float(b);
}
__device__ __forceinline__ float4 fmax4(float4 a, float4 b) {
    return make_float4(fmaxf(a.x,b.x), fmaxf(a.y,b.y),
                       fmaxf(a.z,b.z), fmaxf(a.w,b.w));
}

// Exact per-row selection + normalize + store. v[] is the row payload.
__device__ __forceinline__ void process_row(
    float4 (&v)[8], float* __restrict__ outrow,
    unsigned* __restrict__ cand, int* __restrict__ cnt, int lane)
{
    // per-thread max (31 FMNMX tree)
    float4 m01 = fmax4(v[0], v[1]), m23 = fmax4(v[2], v[3]);
    float4 m45 = fmax4(v[4], v[5]), m67 = fmax4(v[6], v[7]);
    float4 mm  = fmax4(fmax4(m01, m23), fmax4(m45, m67));
    float lmax = fmaxf(fmaxf(mm.x, mm.y), fmaxf(mm.z, mm.w));

    // t = 6th largest DISTINCT thread-max (ballot-free; t <= v6)
    unsigned a = fkey(lmax);
    unsigned kth = 0u;
#pragma unroll
    for (int r = 0; r < TOPK; ++r) {
        unsigned m = redux_max_u32(a);
        kth = m;
        if (a == m) a = 0u;
    }
    const float t = funkey(kth);

    // compact candidates (v >= t)
    if (lane == 0) *cnt = 0;
    __syncwarp();
    if (lmax >= t) {
#pragma unroll
        for (int i = 0; i < 8; ++i) {
            if (v[i].x >= t) cand[atomicAdd(cnt,1)] = fkey(v[i].x);
            if (v[i].y >= t) cand[atomicAdd(cnt,1)] = fkey(v[i].y);
            if (v[i].z >= t) cand[atomicAdd(cnt,1)] = fkey(v[i].z);
            if (v[i].w >= t) cand[atomicAdd(cnt,1)] = fkey(v[i].w);
        }
    }
    __syncwarp();

    // lane-0 insertion top-6 over the n candidates (exact multiset)
    float delta;
    if (lane == 0) {
        const int n = *cnt;
        unsigned s0=0u,s1=0u,s2=0u,s3=0u,s4=0u,s5=0u;   // s0 >= ... >= s5
        for (int i = 0; i < n; ++i) {
            unsigned x = cand[i];
            if (x > s5) {
                if      (x > s0) { s5=s4;s4=s3;s3=s2;s2=s1;s1=s0;s0=x; }
                else if (x > s1) { s5=s4;s4=s3;s3=s2;s2=s1;s1=x; }
                else if (x > s2) { s5=s4;s4=s3;s3=s2;s2=x; }
                else if (x > s3) { s5=s4;s4=s3;s3=x; }
                else if (x > s4) { s5=s4;s4=x; }
                else             { s5=x; }
            }
        }
        delta = funkey(s5) + EPSV;
    }
    delta = __shfl_sync(0xffffffffu, delta, 0);

    // clamp in place, warp sum, normalize, store
    float4 acc = make_float4(0.f, 0.f, 0.f, 0.f);
#pragma unroll
    for (int i = 0; i < 8; ++i) {
        v[i].x = fmaxf(v[i].x - delta, 0.0f);
        v[i].y = fmaxf(v[i].y - delta, 0.0f);
        v[i].z = fmaxf(v[i].z - delta, 0.0f);
        v[i].w = fmaxf(v[i].w - delta, 0.0f);
        acc.x += v[i].x; acc.y += v[i].y; acc.z += v[i].z; acc.w += v[i].w;
    }
    float s = (acc.x + acc.y) + (acc.z + acc.w);
#pragma unroll
    for (int o = 16; o > 0; o >>= 1)
        s += __shfl_xor_sync(0xffffffffu, s, o);
    const float rinv = 1.0f / (s + EPSV);

    float4* op = reinterpret_cast<float4*>(outrow);
#pragma unroll
    for (int i = 0; i < 8; ++i) {
        float4 o4;
        o4.x = v[i].x * rinv; o4.y = v[i].y * rinv;
        o4.z = v[i].z * rinv; o4.w = v[i].w * rinv;
        __stcs(op + lane + 32 * i, o4);
    }
}

__global__ __launch_bounds__(32 * WPB)
void topk_renorm_kernel(const float* __restrict__ in,
                        float* __restrict__ out, int rows) {
    const int lane = threadIdx.x & 31;
    const int warp = threadIdx.x >> 5;
    const int row0 = blockIdx.x * RPB + warp * 2;     // this warp's rows
    const int row1 = row0 + 1;
    if (row0 >= rows) return;

    __shared__ unsigned sh_cand[WPB][COLS];   // reused for both rows
    __shared__ int      sh_cnt[WPB];

    // ---- front-batch ALL 16 LDG.128 (both rows) : MLP=16 ----
    const float4* rp0 = reinterpret_cast<const float4*>(in + (size_t)row0 * COLS);
    const float4* rp1 = reinterpret_cast<const float4*>(in + (size_t)row1 * COLS);
    const bool has1 = (row1 < rows);
    float4 v0[8], v1[8];
#pragma unroll
    for (int i = 0; i < 8; ++i) v0[i] = __ldcs(rp0 + lane + 32 * i);
#pragma unroll
    for (int i = 0; i < 8; ++i)
        v1[i] = has1 ? __ldcs(rp1 + lane + 32 * i)
                     : make_float4(0.f, 0.f, 0.f, 0.f);

    // ---- row 0: select + normalize + store (row 1 loads still in flight) ----
    process_row(v0, out + (size_t)row0 * COLS, sh_cand[warp], &sh_cnt[warp], lane);

    // ---- row 1 ----
    if (has1)
        process_row(v1, out + (size_t)row1 * COLS, sh_cand[warp], &sh_cnt[warp], lane);
}

extern "C" void kernel_launch(void* const* d_in, const int* in_sizes, int n_in,
                              void* d_out, int out_size) {
    const float* in = (const float*)d_in[0];
    float* out = (float*)d_out;
    const int rows = in_sizes[0] / COLS;           // 65536 for reference shape
    const int grid = (rows + RPB - 1) / RPB;
    topk_renorm_kernel<<<grid, 32 * WPB>>>(in, out, rows);
}